// round 5
// baseline (speedup 1.0000x reference)
#include <cuda_runtime.h>
#include <cstdint>

#define Bsz 64
#define Ssz 2048
#define Isz 512
#define Hsz 512

// ============================================================
// Phase 1: xW = x @ W + b   (M=131072, K=512, N=512)
// 128x128 block tile, BK=8, 256 threads, 8x8 thread tile,
// packed f32x2 FMA. 2 CTAs/SM (128-reg cap) hides sync bubbles.
// ============================================================
__global__ __launch_bounds__(256, 2) void sgemm_xw(
    const float* __restrict__ A,    // [M,512] = x
    const float* __restrict__ Wm,   // [512,512] = W_i  (row-major [K][N])
    const float* __restrict__ bias, // [512]
    float* __restrict__ C)          // [M,512] = xW+b (hidden region of d_out)
{
    constexpr int K = 512, N = 512;
    __shared__ float As[8][128];
    __shared__ float Bs[8][128];

    const int tid  = threadIdx.x;
    const int bm   = blockIdx.y, bn = blockIdx.x;
    const int arow = tid >> 1, acol = (tid & 1) << 2;   // A tile: 128 rows x 8 k
    const int brow = tid >> 5, bcol = (tid & 31) << 2;  // B tile: 8 k x 128 cols
    const int tx   = tid & 15, ty = tid >> 4;           // 8x8 thread tile

    const float* Ab = A + (size_t)bm * 128 * K;
    const float* Bb = Wm + bn * 128;

    unsigned long long acc[8][4];
#pragma unroll
    for (int i = 0; i < 8; i++)
#pragma unroll
        for (int j = 0; j < 4; j++) acc[i][j] = 0ull;

    for (int kk = 0; kk < K; kk += 8) {
        float4 av = *(const float4*)(Ab + (size_t)arow * K + kk + acol);
        float4 bv = *(const float4*)(Bb + (size_t)(kk + brow) * N + bcol);
        __syncthreads();   // previous compute done before smem overwrite
        As[acol + 0][arow] = av.x;
        As[acol + 1][arow] = av.y;
        As[acol + 2][arow] = av.z;
        As[acol + 3][arow] = av.w;
        *(float4*)&Bs[brow][bcol] = bv;
        __syncthreads();
#pragma unroll
        for (int k = 0; k < 8; k++) {
            float4 a0 = *(const float4*)&As[k][ty * 8];
            float4 a1 = *(const float4*)&As[k][ty * 8 + 4];
            ulonglong2 b0 = *(const ulonglong2*)&Bs[k][tx * 8];
            ulonglong2 b1 = *(const ulonglong2*)&Bs[k][tx * 8 + 4];
            float ar[8] = {a0.x, a0.y, a0.z, a0.w, a1.x, a1.y, a1.z, a1.w};
            unsigned long long br[4] = {b0.x, b0.y, b1.x, b1.y};
#pragma unroll
            for (int i = 0; i < 8; i++) {
                unsigned long long ad;
                unsigned int au = __float_as_uint(ar[i]);
                asm("mov.b64 %0, {%1, %1};" : "=l"(ad) : "r"(au));
#pragma unroll
                for (int j = 0; j < 4; j++)
                    asm("fma.rn.f32x2 %0, %1, %2, %0;"
                        : "+l"(acc[i][j]) : "l"(ad), "l"(br[j]));
            }
        }
    }

    const int cb = bn * 128 + tx * 8;
    ulonglong2 bb0 = *(const ulonglong2*)&bias[cb];
    ulonglong2 bb1 = *(const ulonglong2*)&bias[cb + 4];
    unsigned long long bz[4] = {bb0.x, bb0.y, bb1.x, bb1.y};
#pragma unroll
    for (int i = 0; i < 8; i++) {
        size_t row = (size_t)bm * 128 + ty * 8 + i;
        float* Crow = C + row * N + cb;
#pragma unroll
        for (int j = 0; j < 4; j++) {
            unsigned long long v;
            asm("add.rn.f32x2 %0, %1, %2;" : "=l"(v) : "l"(acc[i][j]), "l"(bz[j]));
            *(unsigned long long*)(Crow + 2 * j) = v;
        }
    }
}

// ============================================================
// fast tanh: 1 - 2/(exp(2x)+1) via MUFU EX2 + RCP.
// Saturates correctly for large |x|; abs err ~1e-7.
// ============================================================
__device__ __forceinline__ float fast_tanh(float x) {
    float e;
    asm("ex2.approx.f32 %0, %1;" : "=f"(e) : "f"(x * 2.8853900817779268f));
    float r;
    asm("rcp.approx.f32 %0, %1;" : "=f"(r) : "f"(e + 1.0f));
    return fmaf(-2.0f, r, 1.0f);
}

// ============================================================
// Phase 2: persistent cluster RNN scan.
// 16 clusters x 8 CTAs (grid 128), 512 threads/CTA (16 warps).
// Cluster owns 4 batch rows; CTA rank r owns U columns [64r,64r+64),
// 8-way K-split: thread (ks, c) holds U[64ks:64ks+64, 64r+c] in
// 64 registers. Per step:
//   xw prefetch (256 threads) -> FFMA2 partials (all) -> smem reduce
//   -> 256-thread epilogue (fast tanh, DSMEM bcast, STG) ->
//   fused cluster barrier.
// ============================================================
__global__ void __launch_bounds__(512, 1) __cluster_dims__(8, 1, 1)
rnn_scan(const float* __restrict__ U,      // [512,512] row-major [k][h]
         float* __restrict__ hidden,       // [B,S,H]: in = xW+b, out = h
         float* __restrict__ hlast)        // [B,H]
{
    __shared__ float hbuf[2][512][4];      // [buf][k][batch]  (8 KB each)
    __shared__ float red[8][64][4];        // [ksplit][col][batch]

    const int tid = threadIdx.x;
    unsigned int rank;
    asm("mov.u32 %0, %%cluster_ctarank;" : "=r"(rank));
    const int cid = blockIdx.x >> 3;       // cluster id 0..15
    const int b0  = cid * 4;               // 4 batches per cluster
    const int ks  = tid >> 6;              // K split 0..7 (64 k each)
    const int c   = tid & 63;              // local column
    const int cg  = (int)rank * 64 + c;    // global column 0..511

    // One-time: U chunk into registers (64 regs).
    float Ureg[64];
#pragma unroll
    for (int j = 0; j < 64; j++)
        Ureg[j] = U[(size_t)(ks * 64 + j) * Hsz + cg];

    // Epilogue mapping (tid < 256): one (column, batch) value per thread.
    const int ecol = tid & 63;
    const int eb   = (tid >> 6) & 3;
    const int egc  = (int)rank * 64 + ecol;

    // DSMEM targets for buffer 0 (buffer 1 = +8192 bytes).
    unsigned int ra[8];
    if (tid < 256) {
        unsigned int la =
            (unsigned int)__cvta_generic_to_shared(&hbuf[0][egc][eb]);
#pragma unroll
        for (int r = 0; r < 8; r++)
            asm("mapa.shared::cluster.u32 %0, %1, %2;"
                : "=r"(ra[r]) : "r"(la), "r"(r));
    }

    // h0 = 0 (both buffers)
    {
        float* hz = &hbuf[0][0][0];
        for (int i = tid; i < 2 * 512 * 4; i += 512) hz[i] = 0.0f;
    }
    __syncthreads();
    asm volatile("barrier.cluster.arrive.aligned;" ::: "memory");
    asm volatile("barrier.cluster.wait.aligned;" ::: "memory");

    size_t gaddr = 0;
    if (tid < 256)
        gaddr = ((size_t)(b0 + eb) * Ssz) * Hsz + egc;

    for (int t = 0; t < Ssz; t++) {
        const int p = t & 1;

        // xw prefetch for this step (consumed after the FMA loop).
        float xw = 0.0f;
        if (tid < 256)
            xw = __ldg(hidden + gaddr);

        // ---- partial dot products: 4 batches x 1 col x 64 k (f32x2) ----
        const ulonglong2* hk =
            (const ulonglong2*)&hbuf[p][ks * 64][0];   // 16B = one k, 4 batches
        unsigned long long a01a = 0ull, a01b = 0ull, a23a = 0ull, a23b = 0ull;
#pragma unroll
        for (int j = 0; j < 64; j += 2) {
            ulonglong2 h0 = hk[j];
            ulonglong2 h1 = hk[j + 1];
            unsigned long long u0, u1;
            unsigned int uu0 = __float_as_uint(Ureg[j]);
            unsigned int uu1 = __float_as_uint(Ureg[j + 1]);
            asm("mov.b64 %0, {%1, %1};" : "=l"(u0) : "r"(uu0));
            asm("mov.b64 %0, {%1, %1};" : "=l"(u1) : "r"(uu1));
            asm("fma.rn.f32x2 %0, %1, %2, %0;" : "+l"(a01a) : "l"(u0), "l"(h0.x));
            asm("fma.rn.f32x2 %0, %1, %2, %0;" : "+l"(a23a) : "l"(u0), "l"(h0.y));
            asm("fma.rn.f32x2 %0, %1, %2, %0;" : "+l"(a01b) : "l"(u1), "l"(h1.x));
            asm("fma.rn.f32x2 %0, %1, %2, %0;" : "+l"(a23b) : "l"(u1), "l"(h1.y));
        }
        unsigned long long a01, a23;
        asm("add.rn.f32x2 %0, %1, %2;" : "=l"(a01) : "l"(a01a), "l"(a01b));
        asm("add.rn.f32x2 %0, %1, %2;" : "=l"(a23) : "l"(a23a), "l"(a23b));
        unsigned int w0, w1, w2, w3;
        asm("mov.b64 {%0, %1}, %2;" : "=r"(w0), "=r"(w1) : "l"(a01));
        asm("mov.b64 {%0, %1}, %2;" : "=r"(w2), "=r"(w3) : "l"(a23));
        *(float4*)&red[ks][c][0] =
            make_float4(__uint_as_float(w0), __uint_as_float(w1),
                        __uint_as_float(w2), __uint_as_float(w3));
        __syncthreads();

        // ---- epilogue: 256 threads, one value each ----
        if (tid < 256) {
            float s0 = red[0][ecol][eb] + red[1][ecol][eb];
            float s1 = red[2][ecol][eb] + red[3][ecol][eb];
            float s2 = red[4][ecol][eb] + red[5][ecol][eb];
            float s3 = red[6][ecol][eb] + red[7][ecol][eb];
            float v  = fast_tanh(xw + ((s0 + s1) + (s2 + s3)));

            // DSMEM broadcast into hbuf[p^1] of all 8 cluster CTAs.
            const unsigned int off = (unsigned int)(p ^ 1) * 8192u;
#pragma unroll
            for (int r = 0; r < 8; r++)
                asm volatile("st.shared::cluster.f32 [%0], %1;"
                             :: "r"(ra[r] + off), "f"(v) : "memory");

            hidden[gaddr] = v;               // overwrite xw[t] in place
            if (t == Ssz - 1)
                hlast[(size_t)(b0 + eb) * Hsz + egc] = v;
            else
                gaddr += Hsz;                // advance to t+1
        }

        // One cluster barrier per step: releases DSMEM writes, acquires
        // peers' writes into hbuf[p^1].
        asm volatile("barrier.cluster.arrive.aligned;" ::: "memory");
        asm volatile("barrier.cluster.wait.aligned;" ::: "memory");
    }
}

extern "C" void kernel_launch(void* const* d_in, const int* in_sizes, int n_in,
                              void* d_out, int out_size) {
    const float* x  = (const float*)d_in[0];   // [64,2048,512]
    const float* Wi = (const float*)d_in[1];   // [512,512]
    const float* Ui = (const float*)d_in[2];   // [512,512]
    const float* bi = (const float*)d_in[3];   // [512]

    float* hidden = (float*)d_out;                        // [B,S,H]
    float* hlast  = hidden + (size_t)Bsz * Ssz * Hsz;     // [B,H]

    // Phase 1: xW + b -> hidden (in-place staging)
    dim3 g1(Hsz / 128, (Bsz * Ssz) / 128);   // (4, 1024)
    sgemm_xw<<<g1, 256>>>(x, Wi, bi, hidden);

    // Phase 2: sequential scan, persistent cluster kernel.
    rnn_scan<<<128, 512>>>(Ui, hidden, hlast);
}

// round 6
// speedup vs baseline: 2.1799x; 2.1799x over previous
#include <cuda_runtime.h>
#include <cstdint>

#define Bsz 64
#define Ssz 2048
#define Isz 512
#define Hsz 512

// ============================================================
// Phase 1: xW = x @ W + b   (M=131072, K=512, N=512)
// 128x128 block tile, BK=8, 256 threads, 8x8 thread tile,
// packed f32x2 FMA. 2 CTAs/SM (128-reg cap) hides sync bubbles.
// ============================================================
__global__ __launch_bounds__(256, 2) void sgemm_xw(
    const float* __restrict__ A,    // [M,512] = x
    const float* __restrict__ Wm,   // [512,512] = W_i  (row-major [K][N])
    const float* __restrict__ bias, // [512]
    float* __restrict__ C)          // [M,512] = xW+b
{
    constexpr int K = 512, N = 512;
    __shared__ float As[8][128];
    __shared__ float Bs[8][128];

    const int tid  = threadIdx.x;
    const int bm   = blockIdx.y, bn = blockIdx.x;
    const int arow = tid >> 1, acol = (tid & 1) << 2;
    const int brow = tid >> 5, bcol = (tid & 31) << 2;
    const int tx   = tid & 15, ty = tid >> 4;

    const float* Ab = A + (size_t)bm * 128 * K;
    const float* Bb = Wm + bn * 128;

    unsigned long long acc[8][4];
#pragma unroll
    for (int i = 0; i < 8; i++)
#pragma unroll
        for (int j = 0; j < 4; j++) acc[i][j] = 0ull;

    for (int kk = 0; kk < K; kk += 8) {
        float4 av = *(const float4*)(Ab + (size_t)arow * K + kk + acol);
        float4 bv = *(const float4*)(Bb + (size_t)(kk + brow) * N + bcol);
        __syncthreads();
        As[acol + 0][arow] = av.x;
        As[acol + 1][arow] = av.y;
        As[acol + 2][arow] = av.z;
        As[acol + 3][arow] = av.w;
        *(float4*)&Bs[brow][bcol] = bv;
        __syncthreads();
#pragma unroll
        for (int k = 0; k < 8; k++) {
            float4 a0 = *(const float4*)&As[k][ty * 8];
            float4 a1 = *(const float4*)&As[k][ty * 8 + 4];
            ulonglong2 b0 = *(const ulonglong2*)&Bs[k][tx * 8];
            ulonglong2 b1 = *(const ulonglong2*)&Bs[k][tx * 8 + 4];
            float ar[8] = {a0.x, a0.y, a0.z, a0.w, a1.x, a1.y, a1.z, a1.w};
            unsigned long long br[4] = {b0.x, b0.y, b1.x, b1.y};
#pragma unroll
            for (int i = 0; i < 8; i++) {
                unsigned long long ad;
                unsigned int au = __float_as_uint(ar[i]);
                asm("mov.b64 %0, {%1, %1};" : "=l"(ad) : "r"(au));
#pragma unroll
                for (int j = 0; j < 4; j++)
                    asm("fma.rn.f32x2 %0, %1, %2, %0;"
                        : "+l"(acc[i][j]) : "l"(ad), "l"(br[j]));
            }
        }
    }

    const int cb = bn * 128 + tx * 8;
    ulonglong2 bb0 = *(const ulonglong2*)&bias[cb];
    ulonglong2 bb1 = *(const ulonglong2*)&bias[cb + 4];
    unsigned long long bz[4] = {bb0.x, bb0.y, bb1.x, bb1.y};
#pragma unroll
    for (int i = 0; i < 8; i++) {
        size_t row = (size_t)bm * 128 + ty * 8 + i;
        float* Crow = C + row * N + cb;
#pragma unroll
        for (int j = 0; j < 4; j++) {
            unsigned long long v;
            asm("add.rn.f32x2 %0, %1, %2;" : "=l"(v) : "l"(acc[i][j]), "l"(bz[j]));
            *(unsigned long long*)(Crow + 2 * j) = v;
        }
    }
}

// fast tanh: 1 - 2/(exp(2x)+1) via MUFU EX2 + RCP (abs err ~1e-7).
__device__ __forceinline__ float fast_tanh(float x) {
    float e;
    asm("ex2.approx.f32 %0, %1;" : "=f"(e) : "f"(x * 2.8853900817779268f));
    float r;
    asm("rcp.approx.f32 %0, %1;" : "=f"(r) : "f"(e + 1.0f));
    return fmaf(-2.0f, r, 1.0f);
}

__device__ __forceinline__ void mbar_wait(unsigned int addr, unsigned int parity) {
    unsigned int done;
    do {
        asm volatile(
            "{\n\t.reg .pred p;\n\t"
            "mbarrier.try_wait.parity.acquire.cta.shared::cta.b64 p, [%1], %2, 0x989680;\n\t"
            "selp.b32 %0, 1, 0, p;\n\t}"
            : "=r"(done) : "r"(addr), "r"(parity) : "memory");
    } while (!done);
}

// ============================================================
// Phase 2: persistent cluster RNN scan (mbarrier tx protocol).
// 16 clusters x 8 CTAs (grid 128), 256 threads/CTA.
// Cluster owns 4 batch rows; CTA rank r owns U columns [64r,64r+64)
// as pre-packed k-pairs in registers (64 x 64-bit per thread).
// h layout: hbuf[buf][kpair][batch][2] so the FMA loop needs NO
// per-k duplicate movs. Exchange: local smem writes + 7 x 1KB
// cp.async.bulk (smem->remote smem) with complete_tx on the remote
// mbarrier; each CTA waits only its own mbarrier (expect 7168 B).
// ============================================================
__global__ void __launch_bounds__(256, 1) __cluster_dims__(8, 1, 1)
rnn_scan(const float* __restrict__ U,      // [512,512] row-major [k][h]
         float* __restrict__ hidden,       // [B,S,H]: in = xW+b, out = h
         float* __restrict__ hlast)        // [B,H]
{
    __shared__ __align__(128) float hbuf[2][256][4][2];  // 16 KB
    __shared__ __align__(16)  float red[4][64][4];       // 4 KB
    __shared__ __align__(16)  unsigned long long mbar[2];

    const int tid = threadIdx.x;
    unsigned int rank;
    asm("mov.u32 %0, %%cluster_ctarank;" : "=r"(rank));
    const int cid = blockIdx.x >> 3;
    const int b0  = cid * 4;
    const int ks  = tid >> 6;              // 0..3 (k-pair split, 64 kp each)
    const int c   = tid & 63;
    const int cg  = (int)rank * 64 + c;

    // Pre-pack U k-pairs: Upack[j] = (U[2kp][cg], U[2kp+1][cg]), kp = ks*64+j.
    unsigned long long Upack[64];
#pragma unroll
    for (int j = 0; j < 64; j++) {
        int k0 = ks * 128 + 2 * j;
        unsigned int lo = __float_as_uint(U[(size_t)k0 * Hsz + cg]);
        unsigned int hi = __float_as_uint(U[(size_t)(k0 + 1) * Hsz + cg]);
        asm("mov.b64 %0, {%1, %2};" : "=l"(Upack[j]) : "r"(lo), "r"(hi));
    }

    const unsigned int hb_base =
        (unsigned int)__cvta_generic_to_shared(&hbuf[0][0][0][0]);
    const unsigned int mb_base =
        (unsigned int)__cvta_generic_to_shared(&mbar[0]);

    // Init: zero both h buffers; mbarriers count=1; arm mb1 for step 1.
    {
        float* hz = &hbuf[0][0][0][0];
        for (int i = tid; i < 2 * 256 * 4 * 2; i += 256) hz[i] = 0.0f;
    }
    if (tid == 0) {
        asm volatile("mbarrier.init.shared.b64 [%0], %1;"
                     :: "r"(mb_base), "r"(1u) : "memory");
        asm volatile("mbarrier.init.shared.b64 [%0], %1;"
                     :: "r"(mb_base + 8), "r"(1u) : "memory");
        asm volatile("mbarrier.arrive.expect_tx.shared.b64 _, [%0], %1;"
                     :: "r"(mb_base + 8), "r"(7168u) : "memory");
    }
    __syncthreads();
    asm volatile("barrier.cluster.arrive.aligned;" ::: "memory");
    asm volatile("barrier.cluster.wait.aligned;" ::: "memory");

    // Epilogue thread state (tid < 64): column egc, 4 batches.
    const int egc = (int)rank * 64 + tid;
    size_t gaddr = 0;
    if (tid < 64)
        gaddr = ((size_t)b0 * Ssz) * Hsz + egc;

    unsigned int ph0 = 0, ph1 = 0;

    for (int t = 0; t < Ssz; t++) {
        const int q = t & 1;
        const unsigned int mbq = mb_base + (unsigned int)q * 8;

        // xw prefetch (independent of the wait; issue early).
        float xw0 = 0.f, xw1 = 0.f, xw2 = 0.f, xw3 = 0.f;
        if (tid < 64) {
            xw0 = __ldg(hidden + gaddr);
            xw1 = __ldg(hidden + gaddr + (size_t)Ssz * Hsz);
            xw2 = __ldg(hidden + gaddr + 2 * (size_t)Ssz * Hsz);
            xw3 = __ldg(hidden + gaddr + 3 * (size_t)Ssz * Hsz);
        }

        // Wait for this step's h (buffer q), except t=0 (zeros).
        if (t > 0) {
            if (q == 0) { mbar_wait(mbq, ph0); ph0 ^= 1; }
            else        { mbar_wait(mbq, ph1); ph1 ^= 1; }
        }
        // Re-arm mb[q] for its next phase (consumed at t+2).
        if (tid == 0)
            asm volatile("mbarrier.arrive.expect_tx.shared.b64 _, [%0], %1;"
                         :: "r"(mbq), "r"(7168u) : "memory");

        // ---- partials: 4 batches x 1 col x 64 k-pairs, no dup movs ----
        const ulonglong2* hk = (const ulonglong2*)&hbuf[q][ks * 64][0][0];
        unsigned long long a0 = 0ull, a1 = 0ull, a2 = 0ull, a3 = 0ull;
#pragma unroll
        for (int j = 0; j < 64; j++) {
            ulonglong2 p01 = hk[2 * j];       // (h2kp,h2kp+1) for b0, b1
            ulonglong2 p23 = hk[2 * j + 1];   // for b2, b3
            asm("fma.rn.f32x2 %0, %1, %2, %0;" : "+l"(a0) : "l"(Upack[j]), "l"(p01.x));
            asm("fma.rn.f32x2 %0, %1, %2, %0;" : "+l"(a1) : "l"(Upack[j]), "l"(p01.y));
            asm("fma.rn.f32x2 %0, %1, %2, %0;" : "+l"(a2) : "l"(Upack[j]), "l"(p23.x));
            asm("fma.rn.f32x2 %0, %1, %2, %0;" : "+l"(a3) : "l"(Upack[j]), "l"(p23.y));
        }
        // lane reduce (even-k lane + odd-k lane)
        float s0, s1, s2, s3;
        {
            unsigned int l, h;
            asm("mov.b64 {%0, %1}, %2;" : "=r"(l), "=r"(h) : "l"(a0));
            s0 = __uint_as_float(l) + __uint_as_float(h);
            asm("mov.b64 {%0, %1}, %2;" : "=r"(l), "=r"(h) : "l"(a1));
            s1 = __uint_as_float(l) + __uint_as_float(h);
            asm("mov.b64 {%0, %1}, %2;" : "=r"(l), "=r"(h) : "l"(a2));
            s2 = __uint_as_float(l) + __uint_as_float(h);
            asm("mov.b64 {%0, %1}, %2;" : "=r"(l), "=r"(h) : "l"(a3));
            s3 = __uint_as_float(l) + __uint_as_float(h);
        }
        *(float4*)&red[ks][c][0] = make_float4(s0, s1, s2, s3);
        __syncthreads();

        // ---- epilogue (tid < 64): finalize, write own h block locally ----
        if (tid < 64) {
            float4 r0 = *(const float4*)&red[0][tid][0];
            float4 r1 = *(const float4*)&red[1][tid][0];
            float4 r2 = *(const float4*)&red[2][tid][0];
            float4 r3 = *(const float4*)&red[3][tid][0];
            float v0 = fast_tanh(xw0 + (r0.x + r1.x) + (r2.x + r3.x));
            float v1 = fast_tanh(xw1 + (r0.y + r1.y) + (r2.y + r3.y));
            float v2 = fast_tanh(xw2 + (r0.z + r1.z) + (r2.z + r3.z));
            float v3 = fast_tanh(xw3 + (r0.w + r1.w) + (r2.w + r3.w));

            // local write into hbuf[q^1], k-pair layout
            float* lhb = &hbuf[q ^ 1][egc >> 1][0][egc & 1];
            lhb[0] = v0; lhb[2] = v1; lhb[4] = v2; lhb[6] = v3;

            hidden[gaddr]                         = v0;  // overwrite xw[t]
            hidden[gaddr + (size_t)Ssz * Hsz]     = v1;
            hidden[gaddr + 2 * (size_t)Ssz * Hsz] = v2;
            hidden[gaddr + 3 * (size_t)Ssz * Hsz] = v3;
            if (t == Ssz - 1) {
                const size_t lb = (size_t)b0 * Hsz + egc;
                hlast[lb]           = v0;
                hlast[lb + Hsz]     = v1;
                hlast[lb + 2 * Hsz] = v2;
                hlast[lb + 3 * Hsz] = v3;
            } else {
                gaddr += Hsz;
            }
        }
        __syncthreads();   // own block fully written before bulk reads it

        // ---- push own 1KB block to the 7 peers' hbuf[q^1] ----
        if (tid < 7) {
            asm volatile("fence.proxy.async.shared::cta;" ::: "memory");
            const unsigned int off =
                (unsigned int)(q ^ 1) * 8192u + rank * 1024u;
            const unsigned int src = hb_base + off;
            const unsigned int pr  = (rank + 1u + (unsigned int)tid) & 7u;
            unsigned int dst, rmb;
            asm("mapa.shared::cluster.u32 %0, %1, %2;"
                : "=r"(dst) : "r"(src), "r"(pr));
            asm("mapa.shared::cluster.u32 %0, %1, %2;"
                : "=r"(rmb) : "r"(mb_base + (unsigned int)(q ^ 1) * 8u), "r"(pr));
            asm volatile(
                "cp.async.bulk.shared::cluster.shared::cta.mbarrier::complete_tx::bytes "
                "[%0], [%1], %2, [%3];"
                :: "r"(dst), "r"(src), "r"(1024u), "r"(rmb) : "memory");
        }
    }

    // Drain the final inbound phase (step 2047 stores into buffer 0),
    // then cluster-sync so no CTA exits with traffic targeting its smem.
    mbar_wait(mb_base, ph0);
    asm volatile("barrier.cluster.arrive.aligned;" ::: "memory");
    asm volatile("barrier.cluster.wait.aligned;" ::: "memory");
}

extern "C" void kernel_launch(void* const* d_in, const int* in_sizes, int n_in,
                              void* d_out, int out_size) {
    const float* x  = (const float*)d_in[0];   // [64,2048,512]
    const float* Wi = (const float*)d_in[1];   // [512,512]
    const float* Ui = (const float*)d_in[2];   // [512,512]
    const float* bi = (const float*)d_in[3];   // [512]

    float* hidden = (float*)d_out;                        // [B,S,H]
    float* hlast  = hidden + (size_t)Bsz * Ssz * Hsz;     // [B,H]

    dim3 g1(Hsz / 128, (Bsz * Ssz) / 128);   // (4, 1024)
    sgemm_xw<<<g1, 256>>>(x, Wi, bi, hidden);

    rnn_scan<<<128, 256>>>(Ui, hidden, hlast);
}